// round 12
// baseline (speedup 1.0000x reference)
#include <cuda_runtime.h>
#include <cuda_bf16.h>
#include <stdint.h>

// Fused gather-concat:
//   out[r, 0:8]  = proc_pos[process_ids[r], :]   (16x8 f32 -> smem, transposed)
//   out[r, 8:11] = locs_sp[location_ids[r], :]   (500000x3 f32 -> padded float4 table)
//
// R12: persistent warps + TWO-stage software pipeline. Iteration t:
//   - issues gather for tile t+1 (ids prefetched last iteration)
//   - prefetches ids for tile t+2 (DRAM latency hidden over a full iter)
//   - stages + flushes tile t (gather result issued a full iter ago)
// Both long-latency loads are off the critical path; steady state is smem +
// store issue only. Warp-private staging (lane-stride-11 STS, conflict-free),
// flush = 88 contiguous float4 __stcs per 32-row tile.

#define THREADS 256
#define WARPS (THREADS / 32)
#define PROC_DIM 8
#define SP_DIM 3
#define OUT_DIM 11
#define MAX_LOCS 500000
#define TILE 32

__device__ int g_ids_are_i64;
__device__ float4 g_locs_pad[MAX_LOCS];   // 8 MB static scratch

// Pad [num_locs,3] -> float4 table; block 0 also detects the id dtype.
__global__ __launch_bounds__(256)
void setup_kernel(const float* __restrict__ locs_sp, int num_locs,
                  const int* __restrict__ loc_ids_w, int naug)
{
    int i = blockIdx.x * blockDim.x + threadIdx.x;
    if (i < num_locs) {
        const float* s = locs_sp + (size_t)i * SP_DIM;
        float4 v;
        v.x = s[0]; v.y = s[1]; v.z = s[2]; v.w = 0.0f;
        g_locs_pad[i] = v;
    }

    // int64 little-endian ids with values < 5e5 look like (v,0,v,0,...):
    // every odd 32-bit word is zero. Random int32: P(64 zeros) ~ 0.
    if (blockIdx.x == 0) {
        __shared__ int s_not64;
        if (threadIdx.x == 0) s_not64 = 0;
        __syncthreads();
        int n_check = naug < 64 ? naug : 64;
        if (threadIdx.x < n_check) {
            if (loc_ids_w[2 * threadIdx.x + 1] != 0) atomicOr(&s_not64, 1);
        }
        __syncthreads();
        if (threadIdx.x == 0) g_ids_are_i64 = s_not64 ? 0 : 1;
    }
}

__device__ __forceinline__ void load_ids(
    const void* process_ids, const void* location_ids,
    int row, int naug, int ids64, int& rp, int& rl)
{
    if (row < naug) {
        if (ids64) {
            rp = (int)__ldcs(&((const long long*)process_ids)[row]);
            rl = (int)__ldcs(&((const long long*)location_ids)[row]);
        } else {
            rp = __ldcs(&((const int*)process_ids)[row]);
            rl = __ldcs(&((const int*)location_ids)[row]);
        }
    } else {
        rp = 0; rl = 0;
    }
}

__global__ __launch_bounds__(THREADS)
void gather_concat_kernel(
    const float* __restrict__ proc_pos,   // [num_procs, 8]
    const float* __restrict__ locs_sp,    // (unused fast path)
    const void*  __restrict__ process_ids,
    const void*  __restrict__ location_ids,
    float* __restrict__ out,              // [naug, 11]
    int naug,
    int num_procs,
    int num_locs,
    long long ntiles)
{
    __shared__ float s_procT[PROC_DIM * 64];          // transposed [c][pid]
    __shared__ float s_stage[THREADS * OUT_DIM];      // 11264 B, per-warp segments

    const int tid  = threadIdx.x;
    const int warp = tid >> 5;
    const int lane = tid & 31;

    const int proc_elems = num_procs * PROC_DIM;
    for (int i = tid; i < proc_elems; i += THREADS) {
        const int pid = i / PROC_DIM;
        const int c   = i % PROC_DIM;
        s_procT[c * num_procs + pid] = proc_pos[i];
    }
    __syncthreads();   // proc table ready (only block-wide sync)

    const int ids64 = g_ids_are_i64;   // uniform
    float* wstage = &s_stage[warp * TILE * OUT_DIM];   // 1408 B per warp

    const long long gw = (long long)blockIdx.x * WARPS + warp;   // global warp id
    const long long GW = (long long)gridDim.x * WARPS;           // warp stride

    long long t = gw;
    if (t >= ntiles) return;

    // ---- Pipeline prologue ----
    // Stage A: ids + gather for tile t.
    int rp, rl;
    load_ids(process_ids, location_ids, (int)(t * TILE) + lane, naug, ids64, rp, rl);
    int pid = min(max(rp, 0), num_procs - 1);
    int lid = min(max(rl, 0), num_locs - 1);
    float4 v = __ldcg(&g_locs_pad[lid]);

    // Stage B: ids for tile t+GW.
    long long tn = t + GW;
    int rp_n = 0, rl_n = 0;
    if (tn < ntiles)
        load_ids(process_ids, location_ids, (int)(tn * TILE) + lane, naug, ids64, rp_n, rl_n);

    while (t < ntiles) {
        // Issue next tile's gather now (its ids were prefetched last iter).
        const int pid_n = min(max(rp_n, 0), num_procs - 1);
        const int lid_n = min(max(rl_n, 0), num_locs - 1);
        float4 v_n = __ldcg(&g_locs_pad[lid_n]);   // clamped idx: always safe

        // Prefetch ids two tiles ahead.
        const long long tnn = tn + GW;
        int rp_nn = 0, rl_nn = 0;
        if (tnn < ntiles)
            load_ids(process_ids, location_ids, (int)(tnn * TILE) + lane, naug, ids64, rp_nn, rl_nn);

        // Stage + flush tile t using v (issued a full iteration ago).
        const int rb = (int)(t * TILE);
        if (rb + lane < naug) {
            float* dst = &wstage[lane * OUT_DIM];
            #pragma unroll
            for (int c = 0; c < PROC_DIM; c++)
                dst[c] = s_procT[c * num_procs + pid];
            dst[PROC_DIM + 0] = v.x;
            dst[PROC_DIM + 1] = v.y;
            dst[PROC_DIM + 2] = v.z;
        }
        __syncwarp();

        if (rb + TILE <= naug) {
            const float4* s4 = (const float4*)wstage;
            float4* o4 = (float4*)(out + (size_t)rb * OUT_DIM);
            #pragma unroll
            for (int i = lane; i < (TILE * OUT_DIM) / 4; i += 32)
                __stcs(&o4[i], s4[i]);
        } else {
            const int nrows = naug - rb;
            const int total = nrows * OUT_DIM;
            float* o = out + (size_t)rb * OUT_DIM;
            for (int i = lane; i < total; i += 32)
                o[i] = wstage[i];
        }
        __syncwarp();   // protect stage buffer before next iteration's writes

        // Rotate pipeline.
        pid = pid_n; v = v_n;
        rp_n = rp_nn; rl_n = rl_nn;
        t = tn; tn = tnn;
    }
}

extern "C" void kernel_launch(void* const* d_in, const int* in_sizes, int n_in,
                              void* d_out, int out_size) {
    const float* proc_pos     = (const float*)d_in[0];
    const float* locs_sp      = (const float*)d_in[1];
    const void*  process_ids  = d_in[2];
    const void*  location_ids = d_in[3];
    float* out = (float*)d_out;

    const int naug      = in_sizes[2];              // 8,000,000
    const int num_procs = in_sizes[0] / PROC_DIM;   // 16
    const int num_locs  = in_sizes[1] / SP_DIM;     // 500,000

    {
        const int pg = (num_locs + 255) / 256;
        setup_kernel<<<pg, 256>>>(locs_sp, num_locs,
                                  (const int*)location_ids, naug);
    }

    const long long ntiles = ((long long)naug + TILE - 1) / TILE;   // 250000
    long long max_blocks = (ntiles + WARPS - 1) / WARPS;
    int grid = (int)(max_blocks < 1184 ? max_blocks : 1184);
    gather_concat_kernel<<<grid, THREADS>>>(
        proc_pos, locs_sp, process_ids, location_ids, out,
        naug, num_procs, num_locs, ntiles);
}

// round 13
// speedup vs baseline: 1.2047x; 1.2047x over previous
#include <cuda_runtime.h>
#include <cuda_bf16.h>
#include <stdint.h>

// Fused gather-concat:
//   out[r, 0:8]  = proc_pos[process_ids[r], :]   (16x8 f32 -> smem, transposed)
//   out[r, 8:11] = locs_sp[location_ids[r], :]   (500000x3 f32 -> padded float4 table)
//
// R13 = R12's two-stage pipeline with the register bloat removed (R12 regs=40
// dropped occupancy to 57% and regressed). Int tile indices, (pid,lid) packed
// into one int per pipeline stage, clamp folded into the load. Target: <=34
// regs -> 8 blocks/SM. Pipeline: iter t issues gather(t+1), prefetches
// ids(t+2), stages+flushes tile t -> both DRAM id latency and L2 gather
// latency hidden a full iteration. Warp-private staging (lane-stride-11 STS,
// conflict-free); flush = 88 contiguous float4 __stcs per 32-row tile.

#define THREADS 256
#define WARPS (THREADS / 32)
#define PROC_DIM 8
#define SP_DIM 3
#define OUT_DIM 11
#define MAX_LOCS 500000
#define TILE 32

__device__ int g_ids_are_i64;
__device__ float4 g_locs_pad[MAX_LOCS];   // 8 MB static scratch

__global__ __launch_bounds__(256)
void setup_kernel(const float* __restrict__ locs_sp, int num_locs,
                  const int* __restrict__ loc_ids_w, int naug)
{
    int i = blockIdx.x * blockDim.x + threadIdx.x;
    if (i < num_locs) {
        const float* s = locs_sp + (size_t)i * SP_DIM;
        float4 v;
        v.x = s[0]; v.y = s[1]; v.z = s[2]; v.w = 0.0f;
        g_locs_pad[i] = v;
    }
    // int64 little-endian ids with values < 5e5 look like (v,0,v,0,...):
    // every odd 32-bit word is zero. Random int32: P(64 zeros) ~ 0.
    if (blockIdx.x == 0) {
        __shared__ int s_not64;
        if (threadIdx.x == 0) s_not64 = 0;
        __syncthreads();
        int n_check = naug < 64 ? naug : 64;
        if (threadIdx.x < n_check) {
            if (loc_ids_w[2 * threadIdx.x + 1] != 0) atomicOr(&s_not64, 1);
        }
        __syncthreads();
        if (threadIdx.x == 0) g_ids_are_i64 = s_not64 ? 0 : 1;
    }
}

// Load ids for one row, clamp, and pack: (pid << 20) | lid  (lid < 2^20).
__device__ __forceinline__ int load_ids_packed(
    const void* process_ids, const void* location_ids,
    int row, int naug, int ids64, int num_procs, int num_locs)
{
    int rp = 0, rl = 0;
    if (row < naug) {
        if (ids64) {
            rp = (int)__ldcs(&((const long long*)process_ids)[row]);
            rl = (int)__ldcs(&((const long long*)location_ids)[row]);
        } else {
            rp = __ldcs(&((const int*)process_ids)[row]);
            rl = __ldcs(&((const int*)location_ids)[row]);
        }
    }
    rp = min(max(rp, 0), num_procs - 1);
    rl = min(max(rl, 0), num_locs - 1);
    return (rp << 20) | rl;
}

__global__ __launch_bounds__(THREADS)
void gather_concat_kernel(
    const float* __restrict__ proc_pos,
    const void*  __restrict__ process_ids,
    const void*  __restrict__ location_ids,
    float* __restrict__ out,
    int naug,
    int num_procs,
    int num_locs,
    int ntiles)
{
    __shared__ float s_procT[PROC_DIM * 64];          // transposed [c][pid]
    __shared__ float s_stage[THREADS * OUT_DIM];      // per-warp 1408 B segments

    const int tid  = threadIdx.x;
    const int warp = tid >> 5;
    const int lane = tid & 31;

    const int proc_elems = num_procs * PROC_DIM;
    for (int i = tid; i < proc_elems; i += THREADS) {
        s_procT[(i % PROC_DIM) * num_procs + (i / PROC_DIM)] = proc_pos[i];
    }
    __syncthreads();

    const int ids64 = g_ids_are_i64;
    float* wstage = &s_stage[warp * TILE * OUT_DIM];

    const int GW = gridDim.x * WARPS;                  // warp stride (tiles)
    int t = blockIdx.x * WARPS + warp;
    if (t >= ntiles) return;

    // Prologue: stage A = ids+gather for tile t; stage B = ids for t+GW.
    int g = load_ids_packed(process_ids, location_ids, t * TILE + lane,
                            naug, ids64, num_procs, num_locs);
    float4 v = __ldcg(&g_locs_pad[g & 0xFFFFF]);

    int tn = t + GW;
    int g_n = 0;
    if (tn < ntiles)
        g_n = load_ids_packed(process_ids, location_ids, tn * TILE + lane,
                              naug, ids64, num_procs, num_locs);

    while (t < ntiles) {
        // Issue next tile's gather (ids already resident).
        float4 v_n = __ldcg(&g_locs_pad[g_n & 0xFFFFF]);

        // Prefetch ids two tiles ahead.
        const int tnn = tn + GW;
        int g_nn = 0;
        if (tnn < ntiles)
            g_nn = load_ids_packed(process_ids, location_ids, tnn * TILE + lane,
                                   naug, ids64, num_procs, num_locs);

        // Stage + flush tile t (v issued a full iteration ago).
        const int rb = t * TILE;
        const int pid = g >> 20;
        if (rb + lane < naug) {
            float* dst = &wstage[lane * OUT_DIM];
            #pragma unroll
            for (int c = 0; c < PROC_DIM; c++)
                dst[c] = s_procT[c * num_procs + pid];
            dst[PROC_DIM + 0] = v.x;
            dst[PROC_DIM + 1] = v.y;
            dst[PROC_DIM + 2] = v.z;
        }
        __syncwarp();

        if (rb + TILE <= naug) {
            const float4* s4 = (const float4*)wstage;
            float4* o4 = (float4*)(out + (size_t)rb * OUT_DIM);
            #pragma unroll
            for (int i = lane; i < (TILE * OUT_DIM) / 4; i += 32)
                __stcs(&o4[i], s4[i]);
        } else {
            const int total = (naug - rb) * OUT_DIM;
            float* o = out + (size_t)rb * OUT_DIM;
            for (int i = lane; i < total; i += 32)
                o[i] = wstage[i];
        }
        __syncwarp();

        // Rotate.
        g = g_n; v = v_n;
        g_n = g_nn;
        t = tn; tn = tnn;
    }
}

// Safety fallback for num_locs > MAX_LOCS (not hit for this problem).
__global__ __launch_bounds__(THREADS)
void gather_concat_fallback(
    const float* __restrict__ proc_pos,
    const float* __restrict__ locs_sp,
    const void*  __restrict__ process_ids,
    const void*  __restrict__ location_ids,
    float* __restrict__ out,
    int naug, int num_procs, int num_locs)
{
    const long long row = (long long)blockIdx.x * THREADS + threadIdx.x;
    if (row >= naug) return;
    const int ids64 = g_ids_are_i64;
    long long rp, rl;
    if (ids64) {
        rp = ((const long long*)process_ids)[row];
        rl = ((const long long*)location_ids)[row];
    } else {
        rp = ((const int*)process_ids)[row];
        rl = ((const int*)location_ids)[row];
    }
    int pid = (int)min(max(rp, 0LL), (long long)num_procs - 1);
    long long lid = min(max(rl, 0LL), (long long)num_locs - 1);
    float* o = out + (size_t)row * OUT_DIM;
    #pragma unroll
    for (int c = 0; c < PROC_DIM; c++) o[c] = proc_pos[pid * PROC_DIM + c];
    #pragma unroll
    for (int c = 0; c < SP_DIM; c++)  o[PROC_DIM + c] = locs_sp[lid * SP_DIM + c];
}

extern "C" void kernel_launch(void* const* d_in, const int* in_sizes, int n_in,
                              void* d_out, int out_size) {
    const float* proc_pos     = (const float*)d_in[0];
    const float* locs_sp      = (const float*)d_in[1];
    const void*  process_ids  = d_in[2];
    const void*  location_ids = d_in[3];
    float* out = (float*)d_out;

    const int naug      = in_sizes[2];              // 8,000,000
    const int num_procs = in_sizes[0] / PROC_DIM;   // 16
    const int num_locs  = in_sizes[1] / SP_DIM;     // 500,000

    if (num_locs > MAX_LOCS) {
        setup_kernel<<<1, 256>>>(locs_sp, 0, (const int*)location_ids, naug);
        const long long grid = ((long long)naug + THREADS - 1) / THREADS;
        gather_concat_fallback<<<(int)grid, THREADS>>>(
            proc_pos, locs_sp, process_ids, location_ids, out,
            naug, num_procs, num_locs);
        return;
    }

    {
        const int pg = (num_locs + 255) / 256;
        setup_kernel<<<pg, 256>>>(locs_sp, num_locs,
                                  (const int*)location_ids, naug);
    }

    const int ntiles = (naug + TILE - 1) / TILE;    // 250,000
    long long max_blocks = ((long long)ntiles + WARPS - 1) / WARPS;
    int grid = (int)(max_blocks < 1184 ? max_blocks : 1184);
    gather_concat_kernel<<<grid, THREADS>>>(
        proc_pos, process_ids, location_ids, out,
        naug, num_procs, num_locs, ntiles);
}